// round 8
// baseline (speedup 1.0000x reference)
#include <cuda_runtime.h>
#include <cuda_bf16.h>
#include <cstdint>

#define BB 16
#define NW 100
#define HH 8
#define LLEN 64
#define CC 256
#define DH 32
#define LOGIT_MAX 4.6051701859880913680f
#define X_TOTAL (BB*NW*LLEN*CC)

#define ST 40   // bf16 units per smem row (80B): LDSM 8-row phases conflict-free

__device__ __forceinline__ uint32_t smem_u32(const void* p) {
    uint32_t a;
    asm("{ .reg .u64 t; cvta.to.shared.u64 t, %1; cvt.u32.u64 %0, t; }" : "=r"(a) : "l"(p));
    return a;
}

__device__ __forceinline__ uint32_t pack2(float a, float b) {
    __nv_bfloat162 h = __floats2bfloat162_rn(a, b);
    return *reinterpret_cast<uint32_t*>(&h);
}
__device__ __forceinline__ float2 unpack2(uint32_t u) {
    return __bfloat1622float2(*reinterpret_cast<__nv_bfloat162*>(&u));
}

// split float2 -> packed bf16 hi + lo
__device__ __forceinline__ void splitpair(float2 f, uint32_t& hi, uint32_t& lo) {
    hi = pack2(f.x, f.y);
    float2 u = unpack2(hi);
    lo = pack2(f.x - u.x, f.y - u.y);
}

// split 4 floats into packed bf16 hi (uint2) and lo (uint2)
__device__ __forceinline__ void split4(float4 xv, uint2& hi, uint2& lo) {
    hi.x = pack2(xv.x, xv.y);
    hi.y = pack2(xv.z, xv.w);
    float2 f01 = unpack2(hi.x);
    float2 f23 = unpack2(hi.y);
    lo.x = pack2(xv.x - f01.x, xv.y - f01.y);
    lo.y = pack2(xv.z - f23.x, xv.w - f23.y);
}

__device__ __forceinline__ void mma16816(float* c, const uint32_t* a,
                                         uint32_t b0, uint32_t b1) {
    asm volatile(
        "mma.sync.aligned.m16n8k16.row.col.f32.bf16.bf16.f32 "
        "{%0,%1,%2,%3}, {%4,%5,%6,%7}, {%8,%9}, {%0,%1,%2,%3};"
        : "+f"(c[0]), "+f"(c[1]), "+f"(c[2]), "+f"(c[3])
        : "r"(a[0]), "r"(a[1]), "r"(a[2]), "r"(a[3]), "r"(b0), "r"(b1));
}

__device__ __forceinline__ void ldsm4t(uint32_t* r, uint32_t addr) {
    asm volatile("ldmatrix.sync.aligned.m8n8.x4.trans.shared.b16 {%0,%1,%2,%3}, [%4];"
                 : "=r"(r[0]), "=r"(r[1]), "=r"(r[2]), "=r"(r[3]) : "r"(addr));
}

// lane address for a 16x16 bf16 tile at (row0, byte col0) in a stride-80B buffer
__device__ __forceinline__ uint32_t tile_addr(uint32_t base, int lane, int row0, int col0) {
    int mat = lane >> 3, lr = lane & 7;
    int row = row0 + lr + ((mat & 1) << 3);
    int col = col0 + ((mat >> 1) << 4);
    return base + row * (ST * 2) + col;
}

__global__ __launch_bounds__(64)
void tat_hmma_kernel(const float* __restrict__ q, const float* __restrict__ k,
                     const float* __restrict__ v, const float* __restrict__ pos,
                     const float* __restrict__ ls, float* __restrict__ out)
{
    __shared__ __nv_bfloat16 Vhi[LLEN * ST], Vlo[LLEN * ST];   // row-major [k][d]

    const int h   = blockIdx.x;
    const int w   = blockIdx.y;
    const int b   = blockIdx.z;
    const int tid = threadIdx.x;
    const int wid = tid >> 5;     // 0..1, each warp owns 32 rows
    const int lane = tid & 31;
    const int g = lane >> 2;
    const int t = lane & 3;

    const long qkvbase = (long)(b * NW + w) * LLEN * CC;
    const float* qh = q + qkvbase + h * DH;
    const float* kh = k + qkvbase + h * DH;
    const float* vh = v + qkvbase + h * DH;

    // ---- stage V (row-major) in packed bf16 hi/lo ----
    #pragma unroll
    for (int i = 0; i < 8; i++) {
        int idx = tid + 64 * i;          // 0..511
        int r  = idx >> 3;               // 0..63
        int c4 = (idx & 7) * 4;          // 0..28
        float4 vv = *(const float4*)(vh + (long)r * CC + c4);
        uint2 hi, lo;
        split4(vv, hi, lo);
        *(uint2*)&Vhi[r * ST + c4] = hi;
        *(uint2*)&Vlo[r * ST + c4] = lo;
    }
    __syncthreads();

    // ---- Q fragments direct from global (2 m-tiles, hi/lo split) ----
    uint32_t aH[2][2][4], aL[2][2][4];
    #pragma unroll
    for (int mt = 0; mt < 2; mt++) {
        const int r0 = wid * 32 + mt * 16 + g;
        const int r1 = r0 + 8;
        #pragma unroll
        for (int ks = 0; ks < 2; ks++) {
            const int c = ks * 16 + t * 2;
            splitpair(*(const float2*)(qh + (long)r0 * CC + c),
                      aH[mt][ks][0], aL[mt][ks][0]);
            splitpair(*(const float2*)(qh + (long)r1 * CC + c),
                      aH[mt][ks][1], aL[mt][ks][1]);
            splitpair(*(const float2*)(qh + (long)r0 * CC + c + 8),
                      aH[mt][ks][2], aL[mt][ks][2]);
            splitpair(*(const float2*)(qh + (long)r1 * CC + c + 8),
                      aH[mt][ks][3], aL[mt][ks][3]);
        }
    }

    // ---- S = Q K^T; K fragments direct from global, shared across m-tiles ----
    float s[2][8][4];
    #pragma unroll
    for (int mt = 0; mt < 2; mt++)
        #pragma unroll
        for (int j = 0; j < 8; j++)
            #pragma unroll
            for (int c = 0; c < 4; c++) s[mt][j][c] = 0.0f;

    #pragma unroll
    for (int j = 0; j < 8; j++) {
        const int n = j * 8 + g;
        #pragma unroll
        for (int ks = 0; ks < 2; ks++) {
            const int c = ks * 16 + t * 2;
            uint32_t bh0, bl0, bh1, bl1;
            splitpair(*(const float2*)(kh + (long)n * CC + c), bh0, bl0);
            splitpair(*(const float2*)(kh + (long)n * CC + c + 8), bh1, bl1);
            #pragma unroll
            for (int mt = 0; mt < 2; mt++) {
                mma16816(s[mt][j], aH[mt][ks], bh0, bh1);
                mma16816(s[mt][j], aH[mt][ks], bl0, bl1);
                mma16816(s[mt][j], aL[mt][ks], bh0, bh1);
            }
        }
    }

    // ---- scale + position + softmax + attn write + P repack (per m-tile) ----
    const float sc = __expf(fminf(__ldg(ls + h), LOGIT_MAX));
    const float* pb = pos + ((long)(b * HH + h) * LLEN) * LLEN;
    float* attn = out + X_TOTAL + ((long)((b * NW + w) * HH + h)) * (LLEN * LLEN);

    uint32_t pHi[2][4][4], pLo[2][4][4];
    #pragma unroll
    for (int mt = 0; mt < 2; mt++) {
        const int r0 = wid * 32 + mt * 16 + g;
        const int r1 = r0 + 8;

        float mx0 = -1e30f, mx1 = -1e30f;
        #pragma unroll
        for (int j = 0; j < 8; j++) {
            float2 p0 = *(const float2*)(pb + r0 * LLEN + j * 8 + t * 2);
            float2 p1 = *(const float2*)(pb + r1 * LLEN + j * 8 + t * 2);
            s[mt][j][0] = fmaf(s[mt][j][0], sc, p0.x);
            s[mt][j][1] = fmaf(s[mt][j][1], sc, p0.y);
            s[mt][j][2] = fmaf(s[mt][j][2], sc, p1.x);
            s[mt][j][3] = fmaf(s[mt][j][3], sc, p1.y);
            mx0 = fmaxf(mx0, fmaxf(s[mt][j][0], s[mt][j][1]));
            mx1 = fmaxf(mx1, fmaxf(s[mt][j][2], s[mt][j][3]));
        }
        mx0 = fmaxf(mx0, __shfl_xor_sync(0xffffffffu, mx0, 1));
        mx0 = fmaxf(mx0, __shfl_xor_sync(0xffffffffu, mx0, 2));
        mx1 = fmaxf(mx1, __shfl_xor_sync(0xffffffffu, mx1, 1));
        mx1 = fmaxf(mx1, __shfl_xor_sync(0xffffffffu, mx1, 2));

        float sum0 = 0.0f, sum1 = 0.0f;
        #pragma unroll
        for (int j = 0; j < 8; j++) {
            s[mt][j][0] = __expf(s[mt][j][0] - mx0);
            s[mt][j][1] = __expf(s[mt][j][1] - mx0);
            s[mt][j][2] = __expf(s[mt][j][2] - mx1);
            s[mt][j][3] = __expf(s[mt][j][3] - mx1);
            sum0 += s[mt][j][0] + s[mt][j][1];
            sum1 += s[mt][j][2] + s[mt][j][3];
        }
        sum0 += __shfl_xor_sync(0xffffffffu, sum0, 1);
        sum0 += __shfl_xor_sync(0xffffffffu, sum0, 2);
        sum1 += __shfl_xor_sync(0xffffffffu, sum1, 1);
        sum1 += __shfl_xor_sync(0xffffffffu, sum1, 2);
        const float inv0 = __fdividef(1.0f, sum0);
        const float inv1 = __fdividef(1.0f, sum1);

        #pragma unroll
        for (int j = 0; j < 8; j++) {
            s[mt][j][0] *= inv0; s[mt][j][1] *= inv0;
            s[mt][j][2] *= inv1; s[mt][j][3] *= inv1;
            *(float2*)(attn + r0 * LLEN + j * 8 + t * 2) =
                make_float2(s[mt][j][0], s[mt][j][1]);
            *(float2*)(attn + r1 * LLEN + j * 8 + t * 2) =
                make_float2(s[mt][j][2], s[mt][j][3]);
        }

        // repack P fragments (C-layout == A-layout) with hi/lo split
        #pragma unroll
        for (int kk = 0; kk < 4; kk++) {
            const int j0 = 2 * kk, j1 = 2 * kk + 1;
            float2 f;
            pHi[mt][kk][0] = pack2(s[mt][j0][0], s[mt][j0][1]);
            f = unpack2(pHi[mt][kk][0]);
            pLo[mt][kk][0] = pack2(s[mt][j0][0] - f.x, s[mt][j0][1] - f.y);
            pHi[mt][kk][1] = pack2(s[mt][j0][2], s[mt][j0][3]);
            f = unpack2(pHi[mt][kk][1]);
            pLo[mt][kk][1] = pack2(s[mt][j0][2] - f.x, s[mt][j0][3] - f.y);
            pHi[mt][kk][2] = pack2(s[mt][j1][0], s[mt][j1][1]);
            f = unpack2(pHi[mt][kk][2]);
            pLo[mt][kk][2] = pack2(s[mt][j1][0] - f.x, s[mt][j1][1] - f.y);
            pHi[mt][kk][3] = pack2(s[mt][j1][2], s[mt][j1][3]);
            f = unpack2(pHi[mt][kk][3]);
            pLo[mt][kk][3] = pack2(s[mt][j1][2] - f.x, s[mt][j1][3] - f.y);
        }
    }

    // ---- O = P V; V fragments via ldmatrix.trans, shared across m-tiles ----
    const uint32_t sVh = smem_u32(Vhi), sVl = smem_u32(Vlo);
    float* xo = out + qkvbase + h * DH;

    #pragma unroll
    for (int dt = 0; dt < 2; dt++) {
        float o0[2][4], o1[2][4];
        #pragma unroll
        for (int mt = 0; mt < 2; mt++)
            #pragma unroll
            for (int c = 0; c < 4; c++) { o0[mt][c] = 0.f; o1[mt][c] = 0.f; }

        #pragma unroll
        for (int ks = 0; ks < 4; ks++) {
            uint32_t vhf[4], vlf[4];
            ldsm4t(vhf, tile_addr(sVh, lane, ks * 16, 32 * dt));
            ldsm4t(vlf, tile_addr(sVl, lane, ks * 16, 32 * dt));
            #pragma unroll
            for (int mt = 0; mt < 2; mt++) {
                mma16816(o0[mt], pHi[mt][ks], vhf[0], vhf[1]);
                mma16816(o1[mt], pHi[mt][ks], vhf[2], vhf[3]);
                mma16816(o0[mt], pHi[mt][ks], vlf[0], vlf[1]);
                mma16816(o1[mt], pHi[mt][ks], vlf[2], vlf[3]);
                mma16816(o0[mt], pLo[mt][ks], vhf[0], vhf[1]);
                mma16816(o1[mt], pLo[mt][ks], vhf[2], vhf[3]);
            }
        }
        #pragma unroll
        for (int mt = 0; mt < 2; mt++) {
            const int r0 = wid * 32 + mt * 16 + g;
            const int r1 = r0 + 8;
            const int d0 = dt * 16 + t * 2;
            *(float2*)(xo + (long)r0 * CC + d0)     = make_float2(o0[mt][0], o0[mt][1]);
            *(float2*)(xo + (long)r1 * CC + d0)     = make_float2(o0[mt][2], o0[mt][3]);
            *(float2*)(xo + (long)r0 * CC + d0 + 8) = make_float2(o1[mt][0], o1[mt][1]);
            *(float2*)(xo + (long)r1 * CC + d0 + 8) = make_float2(o1[mt][2], o1[mt][3]);
        }
    }
}

extern "C" void kernel_launch(void* const* d_in, const int* in_sizes, int n_in,
                              void* d_out, int out_size)
{
    const float* q   = (const float*)d_in[0];
    const float* k   = (const float*)d_in[1];
    const float* v   = (const float*)d_in[2];
    const float* pos = (const float*)d_in[3];
    const float* ls  = (const float*)d_in[4];
    float* out = (float*)d_out;

    dim3 grid(HH, NW, BB);   // 12800 CTAs of 64 threads
    tat_hmma_kernel<<<grid, 64>>>(q, k, v, pos, ls, out);
}

// round 9
// speedup vs baseline: 1.2229x; 1.2229x over previous
#include <cuda_runtime.h>
#include <cuda_bf16.h>
#include <cstdint>

#define BB 16
#define NW 100
#define HH 8
#define LLEN 64
#define CC 256
#define DH 32
#define LOGIT_MAX 4.6051701859880913680f
#define X_TOTAL (BB*NW*LLEN*CC)

#define ST 40       // bf16 units per staging row (80B): LDSM phases conflict-free
#define PST 68      // fp32 stride for P smem
#define XST 36      // fp32 stride for X smem

// smem region offsets (bytes)
#define OFF_QHI 0
#define OFF_QLO 5120
#define OFF_KHI 10240
#define OFF_KLO 15360
#define OFF_VHI 20480
#define OFF_VLO 25600
#define OFF_P   0          // overlays Q/K after S-MMA  (64*68*4 = 17408 <= 20480)
#define OFF_X   20480      // overlays V after O-MMA   (64*36*4 = 9216  <= 10240)
#define SMEM_TOTAL 30720

__device__ __forceinline__ uint32_t smem_u32(const void* p) {
    uint32_t a;
    asm("{ .reg .u64 t; cvta.to.shared.u64 t, %1; cvt.u32.u64 %0, t; }" : "=r"(a) : "l"(p));
    return a;
}

__device__ __forceinline__ uint32_t pack2(float a, float b) {
    __nv_bfloat162 h = __floats2bfloat162_rn(a, b);
    return *reinterpret_cast<uint32_t*>(&h);
}
__device__ __forceinline__ float2 unpack2(uint32_t u) {
    return __bfloat1622float2(*reinterpret_cast<__nv_bfloat162*>(&u));
}

__device__ __forceinline__ void split4(float4 xv, uint2& hi, uint2& lo) {
    hi.x = pack2(xv.x, xv.y);
    hi.y = pack2(xv.z, xv.w);
    float2 f01 = unpack2(hi.x);
    float2 f23 = unpack2(hi.y);
    lo.x = pack2(xv.x - f01.x, xv.y - f01.y);
    lo.y = pack2(xv.z - f23.x, xv.w - f23.y);
}

__device__ __forceinline__ void mma16816(float* c, const uint32_t* a,
                                         uint32_t b0, uint32_t b1) {
    asm volatile(
        "mma.sync.aligned.m16n8k16.row.col.f32.bf16.bf16.f32 "
        "{%0,%1,%2,%3}, {%4,%5,%6,%7}, {%8,%9}, {%0,%1,%2,%3};"
        : "+f"(c[0]), "+f"(c[1]), "+f"(c[2]), "+f"(c[3])
        : "r"(a[0]), "r"(a[1]), "r"(a[2]), "r"(a[3]), "r"(b0), "r"(b1));
}

__device__ __forceinline__ void ldsm4(uint32_t* r, uint32_t addr) {
    asm volatile("ldmatrix.sync.aligned.m8n8.x4.shared.b16 {%0,%1,%2,%3}, [%4];"
                 : "=r"(r[0]), "=r"(r[1]), "=r"(r[2]), "=r"(r[3]) : "r"(addr));
}
__device__ __forceinline__ void ldsm4t(uint32_t* r, uint32_t addr) {
    asm volatile("ldmatrix.sync.aligned.m8n8.x4.trans.shared.b16 {%0,%1,%2,%3}, [%4];"
                 : "=r"(r[0]), "=r"(r[1]), "=r"(r[2]), "=r"(r[3]) : "r"(addr));
}

// lane address for a 16x16 bf16 tile at (row0, byte col0) in a stride-80B buffer
__device__ __forceinline__ uint32_t tile_addr(uint32_t base, int lane, int row0, int col0) {
    int mat = lane >> 3, lr = lane & 7;
    int row = row0 + lr + ((mat & 1) << 3);
    int col = col0 + ((mat >> 1) << 4);
    return base + row * (ST * 2) + col;
}

__global__ __launch_bounds__(128)
void tat_hmma_kernel(const float* __restrict__ q, const float* __restrict__ k,
                     const float* __restrict__ v, const float* __restrict__ pos,
                     const float* __restrict__ ls, float* __restrict__ out)
{
    __shared__ __align__(16) char SM[SMEM_TOTAL];
    __nv_bfloat16* Qhi = (__nv_bfloat16*)(SM + OFF_QHI);
    __nv_bfloat16* Qlo = (__nv_bfloat16*)(SM + OFF_QLO);
    __nv_bfloat16* Khi = (__nv_bfloat16*)(SM + OFF_KHI);
    __nv_bfloat16* Klo = (__nv_bfloat16*)(SM + OFF_KLO);
    __nv_bfloat16* Vhi = (__nv_bfloat16*)(SM + OFF_VHI);
    __nv_bfloat16* Vlo = (__nv_bfloat16*)(SM + OFF_VLO);
    float* Psm = (float*)(SM + OFF_P);
    float* Xsm = (float*)(SM + OFF_X);

    const int h   = blockIdx.x;
    const int w   = blockIdx.y;
    const int b   = blockIdx.z;
    const int tid = threadIdx.x;
    const int wid = tid >> 5;
    const int lane = tid & 31;
    const int g = lane >> 2;
    const int t = lane & 3;

    const long qkvbase = (long)(b * NW + w) * LLEN * CC;
    const float* qh = q + qkvbase + h * DH;
    const float* kh = k + qkvbase + h * DH;
    const float* vh = v + qkvbase + h * DH;

    // ---- stage Q, K, V (row-major) in packed bf16 hi/lo ----
    #pragma unroll
    for (int i = 0; i < 4; i++) {
        int idx = tid + 128 * i;         // 0..511
        int r  = idx >> 3;               // 0..63
        int c4 = (idx & 7) * 4;          // 0..28
        float4 qv = *(const float4*)(qh + (long)r * CC + c4);
        float4 kv = *(const float4*)(kh + (long)r * CC + c4);
        float4 vv = *(const float4*)(vh + (long)r * CC + c4);
        uint2 hi, lo;
        split4(qv, hi, lo);
        *(uint2*)&Qhi[r * ST + c4] = hi;
        *(uint2*)&Qlo[r * ST + c4] = lo;
        split4(kv, hi, lo);
        *(uint2*)&Khi[r * ST + c4] = hi;
        *(uint2*)&Klo[r * ST + c4] = lo;
        split4(vv, hi, lo);
        *(uint2*)&Vhi[r * ST + c4] = hi;
        *(uint2*)&Vlo[r * ST + c4] = lo;
    }
    __syncthreads();

    const uint32_t sQh = smem_u32(Qhi), sQl = smem_u32(Qlo);
    const uint32_t sKh = smem_u32(Khi), sKl = smem_u32(Klo);
    const uint32_t sVh = smem_u32(Vhi), sVl = smem_u32(Vlo);

    // ---- S = Q K^T (64x64x32), warp owns rows m0..m0+15 ----
    const int m0 = wid * 16;
    const int r0 = m0 + g;
    const int r1 = r0 + 8;

    uint32_t aH[2][4], aL[2][4];
    #pragma unroll
    for (int ks = 0; ks < 2; ks++) {
        ldsm4(aH[ks], tile_addr(sQh, lane, m0, 32 * ks));
        ldsm4(aL[ks], tile_addr(sQl, lane, m0, 32 * ks));
    }

    float s[8][4];
    #pragma unroll
    for (int j = 0; j < 8; j++)
        #pragma unroll
        for (int c = 0; c < 4; c++) s[j][c] = 0.0f;

    #pragma unroll
    for (int nt = 0; nt < 4; nt++) {
        uint32_t bh[2][4], bl[2][4];
        #pragma unroll
        for (int ks = 0; ks < 2; ks++) {
            ldsm4(bh[ks], tile_addr(sKh, lane, nt * 16, 32 * ks));
            ldsm4(bl[ks], tile_addr(sKl, lane, nt * 16, 32 * ks));
        }
        const int j0 = 2 * nt, j1 = 2 * nt + 1;
        #pragma unroll
        for (int ks = 0; ks < 2; ks++) {
            mma16816(s[j0], aH[ks], bh[ks][0], bh[ks][2]);
            mma16816(s[j1], aH[ks], bh[ks][1], bh[ks][3]);
            mma16816(s[j0], aH[ks], bl[ks][0], bl[ks][2]);
            mma16816(s[j1], aH[ks], bl[ks][1], bl[ks][3]);
            mma16816(s[j0], aL[ks], bh[ks][0], bh[ks][2]);
            mma16816(s[j1], aL[ks], bh[ks][1], bh[ks][3]);
        }
    }
    // all warps done reading Q/K smem -> region reusable for P
    __syncthreads();

    // ---- scale + position + softmax (rows r0, r1) ----
    const float sc = __expf(fminf(__ldg(ls + h), LOGIT_MAX));
    const float* pb = pos + ((long)(b * HH + h) * LLEN) * LLEN;

    float mx0 = -1e30f, mx1 = -1e30f;
    #pragma unroll
    for (int j = 0; j < 8; j++) {
        float2 p0 = *(const float2*)(pb + r0 * LLEN + j * 8 + t * 2);
        float2 p1 = *(const float2*)(pb + r1 * LLEN + j * 8 + t * 2);
        s[j][0] = fmaf(s[j][0], sc, p0.x);
        s[j][1] = fmaf(s[j][1], sc, p0.y);
        s[j][2] = fmaf(s[j][2], sc, p1.x);
        s[j][3] = fmaf(s[j][3], sc, p1.y);
        mx0 = fmaxf(mx0, fmaxf(s[j][0], s[j][1]));
        mx1 = fmaxf(mx1, fmaxf(s[j][2], s[j][3]));
    }
    mx0 = fmaxf(mx0, __shfl_xor_sync(0xffffffffu, mx0, 1));
    mx0 = fmaxf(mx0, __shfl_xor_sync(0xffffffffu, mx0, 2));
    mx1 = fmaxf(mx1, __shfl_xor_sync(0xffffffffu, mx1, 1));
    mx1 = fmaxf(mx1, __shfl_xor_sync(0xffffffffu, mx1, 2));

    float sum0 = 0.0f, sum1 = 0.0f;
    #pragma unroll
    for (int j = 0; j < 8; j++) {
        s[j][0] = __expf(s[j][0] - mx0);
        s[j][1] = __expf(s[j][1] - mx0);
        s[j][2] = __expf(s[j][2] - mx1);
        s[j][3] = __expf(s[j][3] - mx1);
        sum0 += s[j][0] + s[j][1];
        sum1 += s[j][2] + s[j][3];
    }
    sum0 += __shfl_xor_sync(0xffffffffu, sum0, 1);
    sum0 += __shfl_xor_sync(0xffffffffu, sum0, 2);
    sum1 += __shfl_xor_sync(0xffffffffu, sum1, 1);
    sum1 += __shfl_xor_sync(0xffffffffu, sum1, 2);
    const float inv0 = __fdividef(1.0f, sum0);
    const float inv1 = __fdividef(1.0f, sum1);

    // normalize + stash P fp32 into smem (coalesced global write later)
    #pragma unroll
    for (int j = 0; j < 8; j++) {
        s[j][0] *= inv0; s[j][1] *= inv0;
        s[j][2] *= inv1; s[j][3] *= inv1;
        *(float2*)&Psm[r0 * PST + j * 8 + t * 2] = make_float2(s[j][0], s[j][1]);
        *(float2*)&Psm[r1 * PST + j * 8 + t * 2] = make_float2(s[j][2], s[j][3]);
    }

    // ---- repack P fragments (C-layout == A-layout) with hi/lo split ----
    uint32_t pHi[4][4], pLo[4][4];
    #pragma unroll
    for (int kk = 0; kk < 4; kk++) {
        const int j0 = 2 * kk, j1 = 2 * kk + 1;
        float2 f;
        pHi[kk][0] = pack2(s[j0][0], s[j0][1]);
        f = unpack2(pHi[kk][0]); pLo[kk][0] = pack2(s[j0][0] - f.x, s[j0][1] - f.y);
        pHi[kk][1] = pack2(s[j0][2], s[j0][3]);
        f = unpack2(pHi[kk][1]); pLo[kk][1] = pack2(s[j0][2] - f.x, s[j0][3] - f.y);
        pHi[kk][2] = pack2(s[j1][0], s[j1][1]);
        f = unpack2(pHi[kk][2]); pLo[kk][2] = pack2(s[j1][0] - f.x, s[j1][1] - f.y);
        pHi[kk][3] = pack2(s[j1][2], s[j1][3]);
        f = unpack2(pHi[kk][3]); pLo[kk][3] = pack2(s[j1][2] - f.x, s[j1][3] - f.y);
    }
    __syncthreads();   // P smem complete

    // ---- attn copy-out: smem -> global, fully coalesced STG.128 ----
    {
        float* attn = out + X_TOTAL + ((long)((b * NW + w) * HH + h)) * (LLEN * LLEN);
        #pragma unroll
        for (int i = 0; i < 8; i++) {
            int c = tid + 128 * i;           // 16B chunk id, 0..1023
            int r  = c >> 4;
            int c4 = (c & 15) * 4;
            float4 tv = *(const float4*)&Psm[r * PST + c4];
            *(float4*)(attn + (long)c * 4) = tv;
        }
    }

    // ---- O = P V; V fragments via ldmatrix.trans (P frags already in regs) ----
    float o0[2][4], o1[2][4];
    #pragma unroll
    for (int dt = 0; dt < 2; dt++)
        #pragma unroll
        for (int c = 0; c < 4; c++) { o0[dt][c] = 0.f; o1[dt][c] = 0.f; }

    #pragma unroll
    for (int dt = 0; dt < 2; dt++) {
        #pragma unroll
        for (int ks = 0; ks < 4; ks++) {
            uint32_t vhf[4], vlf[4];
            ldsm4t(vhf, tile_addr(sVh, lane, ks * 16, 32 * dt));
            ldsm4t(vlf, tile_addr(sVl, lane, ks * 16, 32 * dt));
            mma16816(o0[dt], pHi[ks], vhf[0], vhf[1]);
            mma16816(o1[dt], pHi[ks], vhf[2], vhf[3]);
            mma16816(o0[dt], pHi[ks], vlf[0], vlf[1]);
            mma16816(o1[dt], pHi[ks], vlf[2], vlf[3]);
            mma16816(o0[dt], pLo[ks], vhf[0], vhf[1]);
            mma16816(o1[dt], pLo[ks], vhf[2], vhf[3]);
        }
    }
    __syncthreads();   // all warps done reading V smem -> region reusable for X

    // ---- stash O fp32 into smem ----
    #pragma unroll
    for (int dt = 0; dt < 2; dt++) {
        const int d0 = dt * 16 + t * 2;
        *(float2*)&Xsm[r0 * XST + d0]     = make_float2(o0[dt][0], o0[dt][1]);
        *(float2*)&Xsm[r1 * XST + d0]     = make_float2(o0[dt][2], o0[dt][3]);
        *(float2*)&Xsm[r0 * XST + d0 + 8] = make_float2(o1[dt][0], o1[dt][1]);
        *(float2*)&Xsm[r1 * XST + d0 + 8] = make_float2(o1[dt][2], o1[dt][3]);
    }
    __syncthreads();

    // ---- x copy-out: smem -> global, coalesced per 128B row-slice ----
    {
        float* xo = out + qkvbase + h * DH;
        #pragma unroll
        for (int i = 0; i < 4; i++) {
            int c = tid + 128 * i;           // 16B chunk id, 0..511
            int r  = c >> 3;
            int c4 = (c & 7) * 4;
            float4 tv = *(const float4*)&Xsm[r * XST + c4];
            *(float4*)(xo + (long)r * CC + c4) = tv;
        }
    }
}

extern "C" void kernel_launch(void* const* d_in, const int* in_sizes, int n_in,
                              void* d_out, int out_size)
{
    const float* q   = (const float*)d_in[0];
    const float* k   = (const float*)d_in[1];
    const float* v   = (const float*)d_in[2];
    const float* pos = (const float*)d_in[3];
    const float* ls  = (const float*)d_in[4];
    float* out = (float*)d_out;

    dim3 grid(HH, NW, BB);   // 12800 CTAs of 128 threads
    tat_hmma_kernel<<<grid, 128>>>(q, k, v, pos, ls, out);
}

// round 10
// speedup vs baseline: 1.4956x; 1.2230x over previous
#include <cuda_runtime.h>
#include <cuda_bf16.h>
#include <cstdint>

#define BB 16
#define NW 100
#define HH 8
#define LLEN 64
#define CC 256
#define DH 32
#define LOGIT_MAX 4.6051701859880913680f
#define X_TOTAL (BB*NW*LLEN*CC)

#define RSTRIDE 144          // bytes per staged row: 4 groups x [16B hi | 16B lo] + 16B pad
#define TBYTES (LLEN * RSTRIDE)

__device__ __forceinline__ uint32_t smem_u32(const void* p) {
    uint32_t a;
    asm("{ .reg .u64 t; cvta.to.shared.u64 t, %1; cvt.u32.u64 %0, t; }" : "=r"(a) : "l"(p));
    return a;
}

__device__ __forceinline__ uint32_t pack2(float a, float b) {
    __nv_bfloat162 h = __floats2bfloat162_rn(a, b);
    return *reinterpret_cast<uint32_t*>(&h);
}
__device__ __forceinline__ float2 unpack2(uint32_t u) {
    return __bfloat1622float2(*reinterpret_cast<__nv_bfloat162*>(&u));
}

__device__ __forceinline__ void split4(float4 xv, uint2& hi, uint2& lo) {
    hi.x = pack2(xv.x, xv.y);
    hi.y = pack2(xv.z, xv.w);
    float2 f01 = unpack2(hi.x);
    float2 f23 = unpack2(hi.y);
    lo.x = pack2(xv.x - f01.x, xv.y - f01.y);
    lo.y = pack2(xv.z - f23.x, xv.w - f23.y);
}

__device__ __forceinline__ void mma16816(float* c, const uint32_t* a,
                                         uint32_t b0, uint32_t b1) {
    asm volatile(
        "mma.sync.aligned.m16n8k16.row.col.f32.bf16.bf16.f32 "
        "{%0,%1,%2,%3}, {%4,%5,%6,%7}, {%8,%9}, {%0,%1,%2,%3};"
        : "+f"(c[0]), "+f"(c[1]), "+f"(c[2]), "+f"(c[3])
        : "r"(a[0]), "r"(a[1]), "r"(a[2]), "r"(a[3]), "r"(b0), "r"(b1));
}

__device__ __forceinline__ void ldsm4(uint32_t* r, uint32_t addr) {
    asm volatile("ldmatrix.sync.aligned.m8n8.x4.shared.b16 {%0,%1,%2,%3}, [%4];"
                 : "=r"(r[0]), "=r"(r[1]), "=r"(r[2]), "=r"(r[3]) : "r"(addr));
}
__device__ __forceinline__ void ldsm4t(uint32_t* r, uint32_t addr) {
    asm volatile("ldmatrix.sync.aligned.m8n8.x4.trans.shared.b16 {%0,%1,%2,%3}, [%4];"
                 : "=r"(r[0]), "=r"(r[1]), "=r"(r[2]), "=r"(r[3]) : "r"(addr));
}

// lane address: 16x16 tile at (row0, col group g0 = 8-col units), hi/lo select
__device__ __forceinline__ uint32_t tadr(uint32_t base, int lane, int r0, int g0, int hl) {
    int mat = lane >> 3, lr = lane & 7;
    return base + (uint32_t)(r0 + lr + ((mat & 1) << 3)) * RSTRIDE
                + (uint32_t)(g0 + (mat >> 1)) * 32 + hl * 16;
}

// K row perm inverse: true row n -> staged position (j<<3)|(t<<1)|d
// where j = 2*((n>>4)&3) + ((n>>1)&1), t = (n>>2)&3, d = n&1
__device__ __forceinline__ int prK(int n) {
    int j = (((n >> 4) & 3) << 1) | ((n >> 1) & 1);
    return (j << 3) | (((n >> 2) & 3) << 1) | (n & 1);
}
// V row perm inverse: true row n -> staged position [kk|e|t|d]
// n = [kk|t|e|d] -> p = (kk<<4)|(e<<3)|(t<<1)|d
__device__ __forceinline__ int prV(int n) {
    return (n & 0x30) | (((n >> 1) & 1) << 3) | (((n >> 2) & 3) << 1) | (n & 1);
}

__global__ __launch_bounds__(128)
void tat_hmma_kernel(const float* __restrict__ q, const float* __restrict__ k,
                     const float* __restrict__ v, const float* __restrict__ pos,
                     const float* __restrict__ ls, float* __restrict__ out)
{
    __shared__ __align__(16) char SM[3 * TBYTES];
    char* Qs = SM;
    char* Ks = SM + TBYTES;
    char* Vs = SM + 2 * TBYTES;

    const int h   = blockIdx.x;
    const int w   = blockIdx.y;
    const int b   = blockIdx.z;
    const int tid = threadIdx.x;
    const int wid = tid >> 5;
    const int lane = tid & 31;
    const int g = lane >> 2;
    const int t = lane & 3;

    const long qkvbase = (long)(b * NW + w) * LLEN * CC;
    const float* qh = q + qkvbase + h * DH;
    const float* kh = k + qkvbase + h * DH;
    const float* vh = v + qkvbase + h * DH;

    // ---- stage Q (identity rows), K (perm rows), V (perm rows) ----
    #pragma unroll
    for (int i = 0; i < 4; i++) {
        int idx = tid + 128 * i;         // 0..511
        int r  = idx >> 3;               // 0..63
        int c4 = (idx & 7) * 4;          // 0..28
        uint32_t coff = (uint32_t)((c4 >> 3) * 32 + ((c4 & 4) << 1));
        float4 qv = *(const float4*)(qh + (long)r * CC + c4);
        float4 kv = *(const float4*)(kh + (long)r * CC + c4);
        float4 vv = *(const float4*)(vh + (long)r * CC + c4);
        uint2 hi, lo;
        split4(qv, hi, lo);
        { char* p = Qs + (uint32_t)r * RSTRIDE + coff;
          *(uint2*)p = hi; *(uint2*)(p + 16) = lo; }
        split4(kv, hi, lo);
        { char* p = Ks + (uint32_t)prK(r) * RSTRIDE + coff;
          *(uint2*)p = hi; *(uint2*)(p + 16) = lo; }
        split4(vv, hi, lo);
        { char* p = Vs + (uint32_t)prV(r) * RSTRIDE + coff;
          *(uint2*)p = hi; *(uint2*)(p + 16) = lo; }
    }
    __syncthreads();

    const uint32_t sQ = smem_u32(Qs), sK = smem_u32(Ks), sV = smem_u32(Vs);

    // ---- S = Q K^T (64x64x32), warp owns rows m0..m0+15 ----
    const int m0 = wid * 16;
    const int r0 = m0 + g;
    const int r1 = r0 + 8;

    uint32_t aH[2][4], aL[2][4];
    #pragma unroll
    for (int ks = 0; ks < 2; ks++) {
        ldsm4(aH[ks], tadr(sQ, lane, m0, 2 * ks, 0));
        ldsm4(aL[ks], tadr(sQ, lane, m0, 2 * ks, 1));
    }

    float s[8][4];
    #pragma unroll
    for (int j = 0; j < 8; j++)
        #pragma unroll
        for (int c = 0; c < 4; c++) s[j][c] = 0.0f;

    #pragma unroll
    for (int nt = 0; nt < 4; nt++) {
        uint32_t bh[2][4], bl[2][4];
        #pragma unroll
        for (int ks = 0; ks < 2; ks++) {
            ldsm4(bh[ks], tadr(sK, lane, nt * 16, 2 * ks, 0));
            ldsm4(bl[ks], tadr(sK, lane, nt * 16, 2 * ks, 1));
        }
        const int j0 = 2 * nt, j1 = 2 * nt + 1;
        #pragma unroll
        for (int ks = 0; ks < 2; ks++) {
            mma16816(s[j0], aH[ks], bh[ks][0], bh[ks][2]);
            mma16816(s[j1], aH[ks], bh[ks][1], bh[ks][3]);
            mma16816(s[j0], aH[ks], bl[ks][0], bl[ks][2]);
            mma16816(s[j1], aH[ks], bl[ks][1], bl[ks][3]);
            mma16816(s[j0], aL[ks], bh[ks][0], bh[ks][2]);
            mma16816(s[j1], aL[ks], bh[ks][1], bh[ks][3]);
        }
    }

    // ---- scale + position (float4, contiguous thanks to col perm) + softmax ----
    // s[j][d] (row r0) <-> true col 16*(j>>1) + 4*t + 2*(j&1) + d
    const float sc = __expf(fminf(__ldg(ls + h), LOGIT_MAX));
    const float* pb = pos + ((long)(b * HH + h) * LLEN) * LLEN;

    float mx0 = -1e30f, mx1 = -1e30f;
    #pragma unroll
    for (int qd = 0; qd < 4; qd++) {
        const int j0 = 2 * qd, j1 = 2 * qd + 1;
        const int c0 = 16 * qd + 4 * t;
        float4 p0 = *(const float4*)(pb + r0 * LLEN + c0);
        float4 p1 = *(const float4*)(pb + r1 * LLEN + c0);
        s[j0][0] = fmaf(s[j0][0], sc, p0.x);
        s[j0][1] = fmaf(s[j0][1], sc, p0.y);
        s[j1][0] = fmaf(s[j1][0], sc, p0.z);
        s[j1][1] = fmaf(s[j1][1], sc, p0.w);
        s[j0][2] = fmaf(s[j0][2], sc, p1.x);
        s[j0][3] = fmaf(s[j0][3], sc, p1.y);
        s[j1][2] = fmaf(s[j1][2], sc, p1.z);
        s[j1][3] = fmaf(s[j1][3], sc, p1.w);
        mx0 = fmaxf(mx0, fmaxf(fmaxf(s[j0][0], s[j0][1]), fmaxf(s[j1][0], s[j1][1])));
        mx1 = fmaxf(mx1, fmaxf(fmaxf(s[j0][2], s[j0][3]), fmaxf(s[j1][2], s[j1][3])));
    }
    mx0 = fmaxf(mx0, __shfl_xor_sync(0xffffffffu, mx0, 1));
    mx0 = fmaxf(mx0, __shfl_xor_sync(0xffffffffu, mx0, 2));
    mx1 = fmaxf(mx1, __shfl_xor_sync(0xffffffffu, mx1, 1));
    mx1 = fmaxf(mx1, __shfl_xor_sync(0xffffffffu, mx1, 2));

    float sum0 = 0.0f, sum1 = 0.0f;
    #pragma unroll
    for (int j = 0; j < 8; j++) {
        s[j][0] = __expf(s[j][0] - mx0);
        s[j][1] = __expf(s[j][1] - mx0);
        s[j][2] = __expf(s[j][2] - mx1);
        s[j][3] = __expf(s[j][3] - mx1);
        sum0 += s[j][0] + s[j][1];
        sum1 += s[j][2] + s[j][3];
    }
    sum0 += __shfl_xor_sync(0xffffffffu, sum0, 1);
    sum0 += __shfl_xor_sync(0xffffffffu, sum0, 2);
    sum1 += __shfl_xor_sync(0xffffffffu, sum1, 1);
    sum1 += __shfl_xor_sync(0xffffffffu, sum1, 2);
    const float inv0 = __fdividef(1.0f, sum0);
    const float inv1 = __fdividef(1.0f, sum1);

    // normalize + write attn directly as float4 (contiguous per thread)
    float* attn = out + X_TOTAL + ((long)((b * NW + w) * HH + h)) * (LLEN * LLEN);
    #pragma unroll
    for (int qd = 0; qd < 4; qd++) {
        const int j0 = 2 * qd, j1 = 2 * qd + 1;
        const int c0 = 16 * qd + 4 * t;
        s[j0][0] *= inv0; s[j0][1] *= inv0; s[j1][0] *= inv0; s[j1][1] *= inv0;
        s[j0][2] *= inv1; s[j0][3] *= inv1; s[j1][2] *= inv1; s[j1][3] *= inv1;
        *(float4*)(attn + r0 * LLEN + c0) =
            make_float4(s[j0][0], s[j0][1], s[j1][0], s[j1][1]);
        *(float4*)(attn + r1 * LLEN + c0) =
            make_float4(s[j0][2], s[j0][3], s[j1][2], s[j1][3]);
    }

    // ---- repack P fragments (C-layout == A-layout under the V row perm) ----
    uint32_t pHi[4][4], pLo[4][4];
    #pragma unroll
    for (int kk = 0; kk < 4; kk++) {
        const int j0 = 2 * kk, j1 = 2 * kk + 1;
        float2 f;
        pHi[kk][0] = pack2(s[j0][0], s[j0][1]);
        f = unpack2(pHi[kk][0]); pLo[kk][0] = pack2(s[j0][0] - f.x, s[j0][1] - f.y);
        pHi[kk][1] = pack2(s[j0][2], s[j0][3]);
        f = unpack2(pHi[kk][1]); pLo[kk][1] = pack2(s[j0][2] - f.x, s[j0][3] - f.y);
        pHi[kk][2] = pack2(s[j1][0], s[j1][1]);
        f = unpack2(pHi[kk][2]); pLo[kk][2] = pack2(s[j1][0] - f.x, s[j1][1] - f.y);
        pHi[kk][3] = pack2(s[j1][2], s[j1][3]);
        f = unpack2(pHi[kk][3]); pLo[kk][3] = pack2(s[j1][2] - f.x, s[j1][3] - f.y);
    }

    // ---- O = P V; V fragments via ldmatrix.trans ----
    float* xo = out + qkvbase + h * DH;
    #pragma unroll
    for (int dt = 0; dt < 2; dt++) {
        float o0[4] = {0.f, 0.f, 0.f, 0.f};
        float o1[4] = {0.f, 0.f, 0.f, 0.f};
        #pragma unroll
        for (int ks = 0; ks < 4; ks++) {
            uint32_t vhf[4], vlf[4];
            ldsm4t(vhf, tadr(sV, lane, ks * 16, 2 * dt, 0));
            ldsm4t(vlf, tadr(sV, lane, ks * 16, 2 * dt, 1));
            mma16816(o0, pHi[ks], vhf[0], vhf[1]);
            mma16816(o1, pHi[ks], vhf[2], vhf[3]);
            mma16816(o0, pHi[ks], vlf[0], vlf[1]);
            mma16816(o1, pHi[ks], vlf[2], vlf[3]);
            mma16816(o0, pLo[ks], vhf[0], vhf[1]);
            mma16816(o1, pLo[ks], vhf[2], vhf[3]);
        }
        const int d0 = dt * 16 + t * 2;
        *(float2*)(xo + (long)r0 * CC + d0)     = make_float2(o0[0], o0[1]);
        *(float2*)(xo + (long)r1 * CC + d0)     = make_float2(o0[2], o0[3]);
        *(float2*)(xo + (long)r0 * CC + d0 + 8) = make_float2(o1[0], o1[1]);
        *(float2*)(xo + (long)r1 * CC + d0 + 8) = make_float2(o1[2], o1[3]);
    }
}

extern "C" void kernel_launch(void* const* d_in, const int* in_sizes, int n_in,
                              void* d_out, int out_size)
{
    const float* q   = (const float*)d_in[0];
    const float* k   = (const float*)d_in[1];
    const float* v   = (const float*)d_in[2];
    const float* pos = (const float*)d_in[3];
    const float* ls  = (const float*)d_in[4];
    float* out = (float*)d_out;

    dim3 grid(HH, NW, BB);   // 12800 CTAs of 128 threads
    tat_hmma_kernel<<<grid, 128>>>(q, k, v, pos, ls, out);
}